// round 1
// baseline (speedup 1.0000x reference)
#include <cuda_runtime.h>
#include <stdint.h>

#define C 64
#define NMAX 100000

// Scratch (static __device__ — no allocation allowed)
__device__ __align__(16) float g_Fnt[(size_t)NMAX * C];   // F_n, node-major [n][c]
__device__ __align__(16) float g_Fvt[(size_t)NMAX * C];   // F_v, node-major [n][c]
__device__ __align__(16) float g_sums[(size_t)NMAX * C];  // scatter accumulators [n][c]
__device__ float g_counts[NMAX];
__device__ float g_csum[C];
__device__ float g_csq[C];
__device__ float g_wvT[C * C];  // w transposed [i][o]
__device__ float g_wnT[C * C];

// ---------------------------------------------------------------------------
// Kernel 0: transpose weights once (tiny)
__global__ void transpose_w_kernel(const float* __restrict__ wv,
                                   const float* __restrict__ wn) {
    int k = blockIdx.x * blockDim.x + threadIdx.x;
    if (k < C * C) {
        int o = k >> 6, i = k & 63;
        g_wvT[i * C + o] = wv[k];
        g_wnT[i * C + o] = wn[k];
    }
}

// ---------------------------------------------------------------------------
// Kernel 1: zero the accumulators
__global__ void zero_kernel(int nsum4, int N) {
    int i = blockIdx.x * blockDim.x + threadIdx.x;
    float4 z = make_float4(0.f, 0.f, 0.f, 0.f);
    if (i < nsum4) reinterpret_cast<float4*>(g_sums)[i] = z;
    if (i < N) g_counts[i] = 0.f;
    if (i < C) { g_csum[i] = 0.f; g_csq[i] = 0.f; }
}

// ---------------------------------------------------------------------------
// Kernel 2: dual 1x1 conv (GEMM): F_v[n][c], F_n[n][c] from x[c_in][n]
// Block: 256 threads, 64 nodes per block. Each thread: 2 nodes x 8 channels x 2 mats.
__global__ void __launch_bounds__(256) gemm_kernel(const float* __restrict__ x, int N) {
    __shared__ float swv[C * C];  // [i][o]
    __shared__ float swn[C * C];  // [i][o]
    __shared__ float sx[C * 64];  // [i][node_local]

    int tid = threadIdx.x;
    int n0 = blockIdx.x * 64;

    for (int k = tid; k < C * C; k += 256) {
        swv[k] = g_wvT[k];
        swn[k] = g_wnT[k];
        int i = k >> 6, nl = k & 63;
        int n = n0 + nl;
        sx[k] = (n < N) ? x[(size_t)i * N + n] : 0.f;
    }
    __syncthreads();

    const int c0  = (tid & 7) * 8;   // channel base (8 consecutive channels)
    const int nl0 = (tid >> 3) * 2;  // node-pair base

    float av0[8], av1[8], an0[8], an1[8];
#pragma unroll
    for (int k = 0; k < 8; k++) { av0[k] = av1[k] = an0[k] = an1[k] = 0.f; }

#pragma unroll 16
    for (int i = 0; i < C; i++) {
        float x0 = sx[i * 64 + nl0];
        float x1 = sx[i * 64 + nl0 + 1];
        float4 a0 = *reinterpret_cast<const float4*>(swv + i * C + c0);
        float4 a1 = *reinterpret_cast<const float4*>(swv + i * C + c0 + 4);
        float4 b0 = *reinterpret_cast<const float4*>(swn + i * C + c0);
        float4 b1 = *reinterpret_cast<const float4*>(swn + i * C + c0 + 4);
        float wa[8] = {a0.x, a0.y, a0.z, a0.w, a1.x, a1.y, a1.z, a1.w};
        float wb[8] = {b0.x, b0.y, b0.z, b0.w, b1.x, b1.y, b1.z, b1.w};
#pragma unroll
        for (int k = 0; k < 8; k++) {
            av0[k] += wa[k] * x0;
            av1[k] += wa[k] * x1;
            an0[k] += wb[k] * x0;
            an1[k] += wb[k] * x1;
        }
    }

    int n_a = n0 + nl0;
    if (n_a < N) {
        float4* pv = reinterpret_cast<float4*>(g_Fvt + (size_t)n_a * C + c0);
        pv[0] = make_float4(av0[0], av0[1], av0[2], av0[3]);
        pv[1] = make_float4(av0[4], av0[5], av0[6], av0[7]);
        float4* pn = reinterpret_cast<float4*>(g_Fnt + (size_t)n_a * C + c0);
        pn[0] = make_float4(an0[0], an0[1], an0[2], an0[3]);
        pn[1] = make_float4(an0[4], an0[5], an0[6], an0[7]);
    }
    int n_b = n_a + 1;
    if (n_b < N) {
        float4* pv = reinterpret_cast<float4*>(g_Fvt + (size_t)n_b * C + c0);
        pv[0] = make_float4(av1[0], av1[1], av1[2], av1[3]);
        pv[1] = make_float4(av1[4], av1[5], av1[6], av1[7]);
        float4* pn = reinterpret_cast<float4*>(g_Fnt + (size_t)n_b * C + c0);
        pn[0] = make_float4(an1[0], an1[1], an1[2], an1[3]);
        pn[1] = make_float4(an1[4], an1[5], an1[6], an1[7]);
    }
}

// ---------------------------------------------------------------------------
// Kernel 3: edge gather + scatter via vectorized red.global.add.v4.f32
// 16 threads per edge, each thread handles one float4 (4 channels).
__global__ void __launch_bounds__(256) edge_kernel(const int* __restrict__ gidx,
                                                   const int* __restrict__ ridx,
                                                   int E) {
    unsigned int idx = blockIdx.x * 256u + threadIdx.x;
    int e = (int)(idx >> 4);
    int j = (int)(idx & 15u);
    if (e >= E) return;
    int g = __ldg(&gidx[e]);
    int r = __ldg(&ridx[e]);
    float4 v = __ldg(reinterpret_cast<const float4*>(g_Fnt) + (size_t)g * 16 + j);
    float* dst = g_sums + (size_t)r * C + j * 4;
    asm volatile("red.global.add.v4.f32 [%0], {%1,%2,%3,%4};"
                 :: "l"(dst), "f"(v.x), "f"(v.y), "f"(v.z), "f"(v.w)
                 : "memory");
    if (j == 0) {
        asm volatile("red.global.add.f32 [%0], %1;"
                     :: "l"(g_counts + r), "f"(1.0f)
                     : "memory");
    }
}

// ---------------------------------------------------------------------------
// Kernel 4: pre-BN value = sums/max(cnt,1) + F_v; transpose to [c][n] into out;
// accumulate per-channel sum/sumsq for BN stats.
__global__ void __launch_bounds__(256) combine_kernel(float* __restrict__ out, int N) {
    __shared__ float tile[64][65];
    __shared__ float ssum[C];
    __shared__ float ssq[C];

    int tid = threadIdx.x;
    int n0 = blockIdx.x * 64;
    if (tid < C) { ssum[tid] = 0.f; ssq[tid] = 0.f; }
    __syncthreads();

    int c = tid & 63;
    int nrow0 = tid >> 6;  // 0..3
    float lsum = 0.f, lsq = 0.f;
#pragma unroll
    for (int m = 0; m < 16; m++) {
        int nl = nrow0 + m * 4;
        int n = n0 + nl;
        float v = 0.f;
        if (n < N) {
            float cnt = g_counts[n];
            v = g_sums[(size_t)n * C + c] / fmaxf(cnt, 1.f) + g_Fvt[(size_t)n * C + c];
        }
        tile[c][nl] = v;
        lsum += v;
        lsq += v * v;
    }
    atomicAdd(&ssum[c], lsum);
    atomicAdd(&ssq[c], lsq);
    __syncthreads();

    // write transposed: out[c2 * N + n0 + nl], coalesced in nl
    int nl = tid & 63;
    int c2base = tid >> 6;
    if (n0 + nl < N) {
#pragma unroll
        for (int m = 0; m < 16; m++) {
            int c2 = c2base + m * 4;
            out[(size_t)c2 * N + n0 + nl] = tile[c2][nl];
        }
    }
    if (tid < C) {
        atomicAdd(&g_csum[tid], ssum[tid]);
        atomicAdd(&g_csq[tid], ssq[tid]);
    }
}

// ---------------------------------------------------------------------------
// Kernel 5: BatchNorm (training stats) + affine + PReLU, in place on out[c][n]
__global__ void __launch_bounds__(256) finalize_kernel(float* __restrict__ out,
                                                       const float* __restrict__ gamma,
                                                       const float* __restrict__ beta,
                                                       const float* __restrict__ prelu,
                                                       int N) {
    int c = blockIdx.y;
    int n = blockIdx.x * 256 + threadIdx.x;
    if (n >= N) return;
    float invN = 1.0f / (float)N;
    float mu = g_csum[c] * invN;
    float var = g_csq[c] * invN - mu * mu;
    float scale = rsqrtf(var + 1e-5f) * gamma[c];
    float b = beta[c];
    float a = prelu[0];
    size_t i = (size_t)c * N + n;
    float v = (out[i] - mu) * scale + b;
    out[i] = (v >= 0.f) ? v : a * v;
}

// ---------------------------------------------------------------------------
extern "C" void kernel_launch(void* const* d_in, const int* in_sizes, int n_in,
                              void* d_out, int out_size) {
    const float* x     = (const float*)d_in[0];  // [64, N]
    const float* wv    = (const float*)d_in[1];  // [64, 64]
    const float* wn    = (const float*)d_in[2];  // [64, 64]
    const float* gamma = (const float*)d_in[3];
    const float* beta  = (const float*)d_in[4];
    const float* prelu = (const float*)d_in[5];
    const int*   ridx  = (const int*)d_in[6];    // reduce_index [E]
    const int*   gidx  = (const int*)d_in[7];    // gather_index [E]
    float* out = (float*)d_out;

    int N = in_sizes[0] / C;
    int E = in_sizes[6];
    if (N > NMAX) N = NMAX;  // static scratch bound (problem shape: N=100000)

    transpose_w_kernel<<<(C * C + 255) / 256, 256>>>(wv, wn);

    int nsum4 = N * (C / 4);
    zero_kernel<<<(nsum4 + 255) / 256, 256>>>(nsum4, N);

    gemm_kernel<<<(N + 63) / 64, 256>>>(x, N);

    unsigned long long ethreads = (unsigned long long)E * 16ull;
    unsigned int eblocks = (unsigned int)((ethreads + 255ull) / 256ull);
    edge_kernel<<<eblocks, 256>>>(gidx, ridx, E);

    combine_kernel<<<(N + 63) / 64, 256>>>(out, N);

    dim3 fgrid((N + 255) / 256, C);
    finalize_kernel<<<fgrid, 256>>>(out, gamma, beta, prelu, N);
}

// round 2
// speedup vs baseline: 1.3934x; 1.3934x over previous
#include <cuda_runtime.h>
#include <stdint.h>

#define C 64
#define NMAX 100000
#define EMAX 3200000

// ---------------------------------------------------------------------------
// Static scratch (no allocation allowed)
__device__ __align__(16) float g_Fnt[(size_t)NMAX * C];   // F_n, node-major [n][c]
__device__ __align__(16) float g_Fvt[(size_t)NMAX * C];   // F_v -> overwritten with pre-BN value
__device__ unsigned g_cnt[NMAX];        // degree histogram
__device__ unsigned g_off[NMAX];        // CSR offsets (exclusive scan of cnt)
__device__ unsigned g_cursor[NMAX];     // mutable cursors for CSR fill
__device__ unsigned g_blk[64];          // scan block totals
__device__ unsigned g_blkoff[64];       // scanned block offsets
__device__ int      g_csr[EMAX];        // CSR adjacency (gather_index sorted by dest)
__device__ float    g_csum[C];
__device__ float    g_csq[C];
__device__ float    g_wvT[C * C];       // w transposed [i][o]
__device__ float    g_wnT[C * C];

// ---------------------------------------------------------------------------
// Kernel: transpose weights once (tiny)
__global__ void transpose_w_kernel(const float* __restrict__ wv,
                                   const float* __restrict__ wn) {
    int k = blockIdx.x * blockDim.x + threadIdx.x;
    if (k < C * C) {
        int o = k >> 6, i = k & 63;
        g_wvT[i * C + o] = wv[k];
        g_wnT[i * C + o] = wn[k];
    }
}

// ---------------------------------------------------------------------------
// Kernel: zero counts + channel stats
__global__ void zero_kernel(int N) {
    int i = blockIdx.x * blockDim.x + threadIdx.x;
    if (i < N) g_cnt[i] = 0u;
    if (i < C) { g_csum[i] = 0.f; g_csq[i] = 0.f; }
}

// ---------------------------------------------------------------------------
// Kernel: dual 1x1 conv (GEMM): F_v[n][c], F_n[n][c] from x[c_in][n]
__global__ void __launch_bounds__(256) gemm_kernel(const float* __restrict__ x, int N) {
    __shared__ float swv[C * C];  // [i][o]
    __shared__ float swn[C * C];  // [i][o]
    __shared__ float sx[C * 64];  // [i][node_local]

    int tid = threadIdx.x;
    int n0 = blockIdx.x * 64;

    for (int k = tid; k < C * C; k += 256) {
        swv[k] = g_wvT[k];
        swn[k] = g_wnT[k];
        int i = k >> 6, nl = k & 63;
        int n = n0 + nl;
        sx[k] = (n < N) ? x[(size_t)i * N + n] : 0.f;
    }
    __syncthreads();

    const int c0  = (tid & 7) * 8;   // channel base (8 consecutive channels)
    const int nl0 = (tid >> 3) * 2;  // node-pair base

    float av0[8], av1[8], an0[8], an1[8];
#pragma unroll
    for (int k = 0; k < 8; k++) { av0[k] = av1[k] = an0[k] = an1[k] = 0.f; }

#pragma unroll 16
    for (int i = 0; i < C; i++) {
        float x0 = sx[i * 64 + nl0];
        float x1 = sx[i * 64 + nl0 + 1];
        float4 a0 = *reinterpret_cast<const float4*>(swv + i * C + c0);
        float4 a1 = *reinterpret_cast<const float4*>(swv + i * C + c0 + 4);
        float4 b0 = *reinterpret_cast<const float4*>(swn + i * C + c0);
        float4 b1 = *reinterpret_cast<const float4*>(swn + i * C + c0 + 4);
        float wa[8] = {a0.x, a0.y, a0.z, a0.w, a1.x, a1.y, a1.z, a1.w};
        float wb[8] = {b0.x, b0.y, b0.z, b0.w, b1.x, b1.y, b1.z, b1.w};
#pragma unroll
        for (int k = 0; k < 8; k++) {
            av0[k] += wa[k] * x0;
            av1[k] += wa[k] * x1;
            an0[k] += wb[k] * x0;
            an1[k] += wb[k] * x1;
        }
    }

    int n_a = n0 + nl0;
    if (n_a < N) {
        float4* pv = reinterpret_cast<float4*>(g_Fvt + (size_t)n_a * C + c0);
        pv[0] = make_float4(av0[0], av0[1], av0[2], av0[3]);
        pv[1] = make_float4(av0[4], av0[5], av0[6], av0[7]);
        float4* pn = reinterpret_cast<float4*>(g_Fnt + (size_t)n_a * C + c0);
        pn[0] = make_float4(an0[0], an0[1], an0[2], an0[3]);
        pn[1] = make_float4(an0[4], an0[5], an0[6], an0[7]);
    }
    int n_b = n_a + 1;
    if (n_b < N) {
        float4* pv = reinterpret_cast<float4*>(g_Fvt + (size_t)n_b * C + c0);
        pv[0] = make_float4(av1[0], av1[1], av1[2], av1[3]);
        pv[1] = make_float4(av1[4], av1[5], av1[6], av1[7]);
        float4* pn = reinterpret_cast<float4*>(g_Fnt + (size_t)n_b * C + c0);
        pn[0] = make_float4(an1[0], an1[1], an1[2], an1[3]);
        pn[1] = make_float4(an1[4], an1[5], an1[6], an1[7]);
    }
}

// ---------------------------------------------------------------------------
// Kernel: degree histogram
__global__ void __launch_bounds__(256) hist_kernel(const int* __restrict__ ridx, int E) {
    int e = blockIdx.x * 256 + threadIdx.x;
    if (e < E) atomicAdd(&g_cnt[ridx[e]], 1u);
}

// ---------------------------------------------------------------------------
// Scan pass 1: per-block (2048 elements) exclusive scan + block totals
__global__ void __launch_bounds__(256) scan1_kernel(int N) {
    __shared__ unsigned sdata[256];
    int t = threadIdx.x;
    int base = blockIdx.x * 2048 + t * 8;

    unsigned v[8];
#pragma unroll
    for (int k = 0; k < 8; k++) v[k] = (base + k < N) ? g_cnt[base + k] : 0u;
    // local exclusive scan within thread
    unsigned run = 0;
#pragma unroll
    for (int k = 0; k < 8; k++) { unsigned c = v[k]; v[k] = run; run += c; }
    sdata[t] = run;
    __syncthreads();
    // inclusive scan over 256 thread totals
    for (int off = 1; off < 256; off <<= 1) {
        unsigned y = (t >= off) ? sdata[t - off] : 0u;
        __syncthreads();
        sdata[t] += y;
        __syncthreads();
    }
    unsigned bexcl = (t > 0) ? sdata[t - 1] : 0u;
#pragma unroll
    for (int k = 0; k < 8; k++)
        if (base + k < N) g_off[base + k] = bexcl + v[k];
    if (t == 255) g_blk[blockIdx.x] = sdata[255];
}

// Scan pass 2: exclusive scan of block totals (single block, <=64 blocks)
__global__ void scan2_kernel(int nb) {
    __shared__ unsigned s[64];
    int t = threadIdx.x;
    s[t] = (t < nb) ? g_blk[t] : 0u;
    __syncthreads();
    for (int off = 1; off < 64; off <<= 1) {
        unsigned y = (t >= off) ? s[t - off] : 0u;
        __syncthreads();
        s[t] += y;
        __syncthreads();
    }
    g_blkoff[t] = (t > 0) ? s[t - 1] : 0u;
}

// Scan pass 3: add block offsets, initialize cursors
__global__ void __launch_bounds__(256) scan3_kernel(int N) {
    int i = blockIdx.x * 256 + threadIdx.x;
    if (i < N) {
        unsigned o = g_off[i] + g_blkoff[i >> 11];
        g_off[i] = o;
        g_cursor[i] = o;
    }
}

// ---------------------------------------------------------------------------
// Kernel: CSR fill (bucket edges by destination)
__global__ void __launch_bounds__(256) csr_kernel(const int* __restrict__ ridx,
                                                  const int* __restrict__ gidx, int E) {
    int e = blockIdx.x * 256 + threadIdx.x;
    if (e < E) {
        int r = ridx[e];
        int g = gidx[e];
        unsigned pos = atomicAdd(&g_cursor[r], 1u);
        g_csr[pos] = g;
    }
}

// ---------------------------------------------------------------------------
// Kernel: per-node segmented gather-sum -> mean, + F_v, BN stats.
// One warp per node; lane j (0..15) owns channels 4j..4j+3, half-warps split edges.
__global__ void __launch_bounds__(256) nodered_kernel(int N, int E) {
    __shared__ float ssum[C];
    __shared__ float ssq[C];
    int tid = threadIdx.x;
    if (tid < C) { ssum[tid] = 0.f; ssq[tid] = 0.f; }
    __syncthreads();

    int lane = tid & 31, wid = tid >> 5;
    int j = lane & 15, h = lane >> 4;
    int warps = gridDim.x * 8;
    int gw = blockIdx.x * 8 + wid;

    float sX = 0.f, sY = 0.f, sZ = 0.f, sW = 0.f;   // BN sum accum
    float qX = 0.f, qY = 0.f, qZ = 0.f, qW = 0.f;   // BN sumsq accum

    for (int n = gw; n < N; n += warps) {
        unsigned start = g_off[n];
        unsigned end = (n + 1 < N) ? g_off[n + 1] : (unsigned)E;
        float ax = 0.f, ay = 0.f, az = 0.f, aw = 0.f;
#pragma unroll 2
        for (unsigned ei = start + h; ei < end; ei += 2) {
            int src = g_csr[ei];
            float4 v = __ldg(reinterpret_cast<const float4*>(g_Fnt) + (size_t)src * 16 + j);
            ax += v.x; ay += v.y; az += v.z; aw += v.w;
        }
        // merge the two half-warp partials
        ax += __shfl_xor_sync(0xffffffffu, ax, 16);
        ay += __shfl_xor_sync(0xffffffffu, ay, 16);
        az += __shfl_xor_sync(0xffffffffu, az, 16);
        aw += __shfl_xor_sync(0xffffffffu, aw, 16);

        if (h == 0) {
            float inv = 1.f / fmaxf((float)(end - start), 1.f);
            float4* p = reinterpret_cast<float4*>(g_Fvt) + (size_t)n * 16 + j;
            float4 fv = *p;
            float vx = ax * inv + fv.x;
            float vy = ay * inv + fv.y;
            float vz = az * inv + fv.z;
            float vw = aw * inv + fv.w;
            *p = make_float4(vx, vy, vz, vw);
            sX += vx; sY += vy; sZ += vz; sW += vw;
            qX += vx * vx; qY += vy * vy; qZ += vz * vz; qW += vw * vw;
        }
    }

    if (h == 0) {
        int cb = j * 4;
        atomicAdd(&ssum[cb + 0], sX); atomicAdd(&ssum[cb + 1], sY);
        atomicAdd(&ssum[cb + 2], sZ); atomicAdd(&ssum[cb + 3], sW);
        atomicAdd(&ssq[cb + 0], qX);  atomicAdd(&ssq[cb + 1], qY);
        atomicAdd(&ssq[cb + 2], qZ);  atomicAdd(&ssq[cb + 3], qW);
    }
    __syncthreads();
    if (tid < C) {
        atomicAdd(&g_csum[tid], ssum[tid]);
        atomicAdd(&g_csq[tid], ssq[tid]);
    }
}

// ---------------------------------------------------------------------------
// Kernel: BN normalize + affine + PReLU + transpose [n][c] -> out [c][n]
__global__ void __launch_bounds__(256) bnfinal_kernel(float* __restrict__ out,
                                                      const float* __restrict__ gamma,
                                                      const float* __restrict__ beta,
                                                      const float* __restrict__ prelu,
                                                      int N) {
    __shared__ float tile[64][65];
    int tid = threadIdx.x;
    int n0 = blockIdx.x * 64;

    int c = tid & 63;
    int nrow0 = tid >> 6;

    float invN = 1.0f / (float)N;
    float mu = g_csum[c] * invN;
    float var = g_csq[c] * invN - mu * mu;
    float scale = rsqrtf(var + 1e-5f) * gamma[c];
    float shift = beta[c] - mu * scale;
    float a = prelu[0];

#pragma unroll
    for (int m = 0; m < 16; m++) {
        int nl = nrow0 + m * 4;
        int n = n0 + nl;
        float v = 0.f;
        if (n < N) {
            v = g_Fvt[(size_t)n * C + c] * scale + shift;
            v = (v >= 0.f) ? v : a * v;
        }
        tile[c][nl] = v;
    }
    __syncthreads();

    int nl = tid & 63;
    int c2b = tid >> 6;
    if (n0 + nl < N) {
#pragma unroll
        for (int m = 0; m < 16; m++) {
            int c2 = c2b + m * 4;
            out[(size_t)c2 * N + n0 + nl] = tile[c2][nl];
        }
    }
}

// ---------------------------------------------------------------------------
extern "C" void kernel_launch(void* const* d_in, const int* in_sizes, int n_in,
                              void* d_out, int out_size) {
    const float* x     = (const float*)d_in[0];  // [64, N]
    const float* wv    = (const float*)d_in[1];  // [64, 64]
    const float* wn    = (const float*)d_in[2];  // [64, 64]
    const float* gamma = (const float*)d_in[3];
    const float* beta  = (const float*)d_in[4];
    const float* prelu = (const float*)d_in[5];
    const int*   ridx  = (const int*)d_in[6];    // reduce_index [E]
    const int*   gidx  = (const int*)d_in[7];    // gather_index [E]
    float* out = (float*)d_out;

    int N = in_sizes[0] / C;
    int E = in_sizes[6];
    if (N > NMAX) N = NMAX;
    if (E > EMAX) E = EMAX;

    transpose_w_kernel<<<(C * C + 255) / 256, 256>>>(wv, wn);
    zero_kernel<<<(N + 255) / 256, 256>>>(N);
    gemm_kernel<<<(N + 63) / 64, 256>>>(x, N);

    hist_kernel<<<(E + 255) / 256, 256>>>(ridx, E);

    int nb = (N + 2047) / 2048;   // <= 49 for NMAX
    scan1_kernel<<<nb, 256>>>(N);
    scan2_kernel<<<1, 64>>>(nb);
    scan3_kernel<<<(N + 255) / 256, 256>>>(N);

    csr_kernel<<<(E + 255) / 256, 256>>>(ridx, gidx, E);

    nodered_kernel<<<1184, 256>>>(N, E);

    bnfinal_kernel<<<(N + 63) / 64, 256>>>(out, gamma, beta, prelu, N);
}